// round 4
// baseline (speedup 1.0000x reference)
#include <cuda_runtime.h>
#include <cstdint>
#include <cstddef>

// Problem constants
#define BB 4
#define SS 2048
#define DD 1024
#define HH 16
#define LL 8
#define VV 8192
#define HDIM 64
#define MTOK (BB*SS)   // 8192 tokens

typedef unsigned long long ull;

// ---------------------------------------------------------------------------
// Static device scratch (no allocations allowed)
// ---------------------------------------------------------------------------
__device__ float g_x   [(size_t)MTOK * DD];        // residual stream   32 MB
__device__ float g_h   [(size_t)MTOK * DD];        // layernorm output  32 MB
__device__ float g_qkv [(size_t)MTOK * 3 * DD];    // qkv projections   96 MB
__device__ float g_attn[(size_t)MTOK * DD];        // attention output  32 MB
__device__ float g_fc  [(size_t)MTOK * 4 * DD];    // MLP hidden       128 MB

// ---------------------------------------------------------------------------
// Packed f32x2 helpers (sm_103a FFMA2 path: 2x FFMA throughput)
// ---------------------------------------------------------------------------
__device__ __forceinline__ void fma2(ull& d, ull a, ull b) {
    asm("fma.rn.f32x2 %0, %1, %2, %0;" : "+l"(d) : "l"(a), "l"(b));
}
__device__ __forceinline__ ull mul2(ull a, ull b) {
    ull d; asm("mul.rn.f32x2 %0, %1, %2;" : "=l"(d) : "l"(a), "l"(b)); return d;
}
__device__ __forceinline__ ull pack2(float x, float y) {
    ull d; asm("mov.b64 %0, {%1, %2};" : "=l"(d) : "f"(x), "f"(y)); return d;
}
__device__ __forceinline__ float2 unpack2(ull v) {
    float2 r; asm("mov.b64 {%0, %1}, %2;" : "=f"(r.x), "=f"(r.y) : "l"(v)); return r;
}

__device__ __forceinline__ float gelu_f(float x) {
    // tanh-approx GELU; tanh(z) = 1 - 2/(exp(2z)+1) (safe at +/-inf)
    float z = 0.7978845608028654f * (x + 0.044715f * x * x * x);
    float e = __expf(2.0f * z);
    float th = 1.0f - 2.0f / (e + 1.0f);
    return 0.5f * x * (1.0f + th);
}

// ---------------------------------------------------------------------------
// Embedding: x[b,s,:] = wte[idx[b,s],:] + wpe[s,:]
// ---------------------------------------------------------------------------
__global__ void embed_k(const int* __restrict__ idx, const float* __restrict__ wte,
                        const float* __restrict__ wpe, float* __restrict__ x) {
    int row = blockIdx.x;              // token 0..8191
    int s   = row & (SS - 1);
    int t   = threadIdx.x;             // 256 threads, one float4 each
    int tok = idx[row];
    float4 a = ((const float4*)(wte + (size_t)tok * DD))[t];
    float4 p = ((const float4*)(wpe + (size_t)s * DD))[t];
    float4 o = make_float4(a.x + p.x, a.y + p.y, a.z + p.z, a.w + p.w);
    ((float4*)(x + (size_t)row * DD))[t] = o;
}

// ---------------------------------------------------------------------------
// LayerNorm (biased var, eps 1e-5). One block per row, 256 threads.
// ---------------------------------------------------------------------------
__global__ void ln_k(const float* __restrict__ x, const float* __restrict__ w,
                     const float* __restrict__ b, float* __restrict__ o) {
    int row = blockIdx.x;
    int t   = threadIdx.x;
    float4 v = ((const float4*)(x + (size_t)row * DD))[t];
    float s = v.x + v.y + v.z + v.w;
    float q = v.x * v.x + v.y * v.y + v.z * v.z + v.w * v.w;
    #pragma unroll
    for (int off = 16; off; off >>= 1) {
        s += __shfl_xor_sync(0xffffffffu, s, off);
        q += __shfl_xor_sync(0xffffffffu, q, off);
    }
    __shared__ float ss[8], sq[8];
    __shared__ float smu, srs;
    int wid = t >> 5;
    if ((t & 31) == 0) { ss[wid] = s; sq[wid] = q; }
    __syncthreads();
    if (t == 0) {
        float S = 0.f, Q = 0.f;
        #pragma unroll
        for (int i = 0; i < 8; i++) { S += ss[i]; Q += sq[i]; }
        float mu  = S * (1.0f / DD);
        float var = Q * (1.0f / DD) - mu * mu;
        smu = mu;
        srs = rsqrtf(var + 1e-5f);
    }
    __syncthreads();
    float mu = smu, r = srs;
    float4 wv = ((const float4*)w)[t];
    float4 bv = ((const float4*)b)[t];
    float4 out;
    out.x = (v.x - mu) * r * wv.x + bv.x;
    out.y = (v.y - mu) * r * wv.y + bv.y;
    out.z = (v.z - mu) * r * wv.z + bv.z;
    out.w = (v.w - mu) * r * wv.w + bv.w;
    ((float4*)(o + (size_t)row * DD))[t] = out;
}

// ---------------------------------------------------------------------------
// NT GEMM: C[M,N] = A[M,K] @ B[N,K]^T (+bias, epilogue)
// Tile 128x128x16, 256 threads, 8x8 per-thread microtile computed in f32x2
// pairs. A-tile stored DUPLICATED in smem so a-pair loads need no packing.
// EPI: 0 = +bias, 1 = gelu(+bias), 2 = C += acc+bias (residual), 3 = no bias
// ---------------------------------------------------------------------------
template<int EPI>
__global__ __launch_bounds__(256, 2) void gemm_nt(
    const float* __restrict__ A, const float* __restrict__ Bm,
    const float* __restrict__ bias, float* __restrict__ C,
    int M, int N, int K)
{
    __shared__ __align__(16) float As2[16][256];   // [k][2*m] duplicated pairs
    __shared__ __align__(16) float Bs [16][128];   // [k][n]

    int tid = threadIdx.x;
    int tx  = tid & 15, ty = tid >> 4;
    int brow = blockIdx.y << 7;
    int bcol = blockIdx.x << 7;

    // global-load assignment: 2 float4 (8 consecutive k floats) per thread
    int lrow = tid >> 1;              // 0..127
    int lc4  = (tid & 1) << 1;        // 0 or 2 (float4 index within 16-float k-tile)

    const float4* A4 = (const float4*)(A  + (size_t)(brow + lrow) * K);
    const float4* B4 = (const float4*)(Bm + (size_t)(bcol + lrow) * K);

    ull acc[8][4];
    #pragma unroll
    for (int i = 0; i < 8; i++)
        #pragma unroll
        for (int j = 0; j < 4; j++) acc[i][j] = 0ull;

    int nk = K >> 4;
    float4 pa0 = A4[lc4], pa1 = A4[lc4 + 1];
    float4 pb0 = B4[lc4], pb1 = B4[lc4 + 1];

    for (int tt = 0; tt < nk; tt++) {
        int kb = lc4 << 2;            // 0 or 8
        float va[8] = {pa0.x, pa0.y, pa0.z, pa0.w, pa1.x, pa1.y, pa1.z, pa1.w};
        float vb[8] = {pb0.x, pb0.y, pb0.z, pb0.w, pb1.x, pb1.y, pb1.z, pb1.w};
        #pragma unroll
        for (int s2 = 0; s2 < 8; s2++) {
            *(float2*)&As2[kb + s2][2 * lrow] = make_float2(va[s2], va[s2]);
            Bs[kb + s2][lrow] = vb[s2];
        }
        __syncthreads();
        if (tt + 1 < nk) {
            int off = (tt + 1) << 2;
            pa0 = A4[off + lc4]; pa1 = A4[off + lc4 + 1];
            pb0 = B4[off + lc4]; pb1 = B4[off + lc4 + 1];
        }
        #pragma unroll
        for (int kk = 0; kk < 16; kk++) {
            ulonglong2 a0 = *(const ulonglong2*)&As2[kk][ty * 16];
            ulonglong2 a1 = *(const ulonglong2*)&As2[kk][ty * 16 + 4];
            ulonglong2 a2 = *(const ulonglong2*)&As2[kk][ty * 16 + 8];
            ulonglong2 a3 = *(const ulonglong2*)&As2[kk][ty * 16 + 12];
            ulonglong2 b0 = *(const ulonglong2*)&Bs[kk][tx * 4];
            ulonglong2 b1 = *(const ulonglong2*)&Bs[kk][64 + tx * 4];
            ull ap[8] = {a0.x, a0.y, a1.x, a1.y, a2.x, a2.y, a3.x, a3.y};
            ull bp[4] = {b0.x, b0.y, b1.x, b1.y};
            #pragma unroll
            for (int i = 0; i < 8; i++)
                #pragma unroll
                for (int j = 0; j < 4; j++)
                    fma2(acc[i][j], ap[i], bp[j]);
        }
        __syncthreads();
    }

    // Epilogue: cols split as [tx*4 .. +3] and [64+tx*4 .. +3]
    int c0 = bcol + (tx << 2), c1 = c0 + 64;
    float4 bv0 = make_float4(0.f, 0.f, 0.f, 0.f), bv1 = bv0;
    if (EPI != 3) {
        bv0 = *(const float4*)(bias + c0);
        bv1 = *(const float4*)(bias + c1);
    }
    #pragma unroll
    for (int i = 0; i < 8; i++) {
        size_t ro = (size_t)(brow + (ty << 3) + i) * N;
        float2 p0 = unpack2(acc[i][0]), p1 = unpack2(acc[i][1]);
        float2 p2 = unpack2(acc[i][2]), p3 = unpack2(acc[i][3]);
        float4 r0 = make_float4(p0.x + bv0.x, p0.y + bv0.y, p1.x + bv0.z, p1.y + bv0.w);
        float4 r1 = make_float4(p2.x + bv1.x, p2.y + bv1.y, p3.x + bv1.z, p3.y + bv1.w);
        if (EPI == 1) {
            r0.x = gelu_f(r0.x); r0.y = gelu_f(r0.y); r0.z = gelu_f(r0.z); r0.w = gelu_f(r0.w);
            r1.x = gelu_f(r1.x); r1.y = gelu_f(r1.y); r1.z = gelu_f(r1.z); r1.w = gelu_f(r1.w);
        }
        if (EPI == 2) {
            float4 o0 = *(const float4*)&C[ro + c0];
            float4 o1 = *(const float4*)&C[ro + c1];
            r0.x += o0.x; r0.y += o0.y; r0.z += o0.z; r0.w += o0.w;
            r1.x += o1.x; r1.y += o1.y; r1.z += o1.z; r1.w += o1.w;
        }
        *(float4*)&C[ro + c0] = r0;
        *(float4*)&C[ro + c1] = r1;
    }
}

// ---------------------------------------------------------------------------
// Flash attention (causal). qkv layout per token row: [K | Q | V], head h at
// chunk offset h*64. One block = 64 q-rows of one (b,h); 64 threads, one
// thread per q-row; online softmax; all dots/accumulates in f32x2.
// ---------------------------------------------------------------------------
__global__ __launch_bounds__(64) void attn_k(const float* __restrict__ qkv,
                                             float* __restrict__ out) {
    __shared__ __align__(16) float Ks[64][64];
    __shared__ __align__(16) float Vs[64][64];
    __shared__ float Ssc[64][65];   // per-row score staging (pitch 65: conflict-free)

    int b = blockIdx.z, h = blockIdx.y, qt = blockIdx.x;
    int t = threadIdx.x;
    int row = (qt << 6) + t;

    const ulonglong2* qp =
        (const ulonglong2*)(qkv + (size_t)(b * SS + row) * (3 * DD) + DD + h * HDIM);
    ull q2[32];
    #pragma unroll
    for (int u = 0; u < 16; u++) { ulonglong2 v = qp[u]; q2[2*u] = v.x; q2[2*u+1] = v.y; }

    ull o2[32];
    #pragma unroll
    for (int u = 0; u < 32; u++) o2[u] = 0ull;
    float m = -1e30f, l = 0.0f;

    for (int kt = 0; kt <= qt; kt++) {
        __syncthreads();
        // cooperative K/V tile load (64x64 each)
        #pragma unroll
        for (int i = 0; i < 16; i++) {
            int Lr = t + (i << 6);
            int r  = Lr >> 4, c4 = Lr & 15;
            size_t base = (size_t)(b * SS + (kt << 6) + r) * (3 * DD) + h * HDIM;
            ((float4*)Ks[r])[c4] = ((const float4*)(qkv + base))[c4];
            ((float4*)Vs[r])[c4] = ((const float4*)(qkv + base + 2 * DD))[c4];
        }
        __syncthreads();

        int jmax = (kt == qt) ? t : 63;
        // phase 1: scores for this tile
        for (int j = 0; j < 64; j++) {
            ull s2 = 0ull;
            const ulonglong2* kp = (const ulonglong2*)Ks[j];
            #pragma unroll
            for (int u = 0; u < 16; u++) {
                ulonglong2 kv = kp[u];
                fma2(s2, q2[2*u],   kv.x);
                fma2(s2, q2[2*u+1], kv.y);
            }
            float2 sf = unpack2(s2);
            float s = (sf.x + sf.y) * 0.125f;           // 1/sqrt(64)
            Ssc[t][j] = (j <= jmax) ? s : -1e30f;
        }
        // phase 2: online softmax update (one rescale per tile)
        float tm = -1e30f;
        for (int j = 0; j < 64; j++) tm = fmaxf(tm, Ssc[t][j]);
        float mn = fmaxf(m, tm);
        float c  = __expf(m - mn);
        l *= c;
        ull c2 = pack2(c, c);
        #pragma unroll
        for (int u = 0; u < 32; u++) o2[u] = mul2(o2[u], c2);
        for (int j = 0; j < 64; j++) {
            float p = __expf(Ssc[t][j] - mn);
            l += p;
            ull p2 = pack2(p, p);
            const ulonglong2* vp = (const ulonglong2*)Vs[j];
            #pragma unroll
            for (int u = 0; u < 16; u++) {
                ulonglong2 vv = vp[u];
                fma2(o2[2*u],   p2, vv.x);
                fma2(o2[2*u+1], p2, vv.y);
            }
        }
        m = mn;
    }

    float inv = 1.0f / l;
    float* op = out + (size_t)(b * SS + row) * DD + h * HDIM;
    #pragma unroll
    for (int u = 0; u < 32; u++) {
        float2 f = unpack2(o2[u]);
        *(float2*)(op + 2 * u) = make_float2(f.x * inv, f.y * inv);
    }
}

// ---------------------------------------------------------------------------
// Orchestration (graph-capturable: kernel launches only)
// ---------------------------------------------------------------------------
extern "C" void kernel_launch(void* const* d_in, const int* in_sizes, int n_in,
                              void* d_out, int out_size) {
    const int*   idx    = (const int*)  d_in[0];
    const float* wte    = (const float*)d_in[1];
    const float* wpe    = (const float*)d_in[2];
    const float* ln1w   = (const float*)d_in[3];
    const float* ln1b   = (const float*)d_in[4];
    const float* qkvw   = (const float*)d_in[5];
    const float* qkvb   = (const float*)d_in[6];
    const float* projw  = (const float*)d_in[7];
    const float* projb  = (const float*)d_in[8];
    const float* ln2w   = (const float*)d_in[9];
    const float* ln2b   = (const float*)d_in[10];
    const float* fcw    = (const float*)d_in[11];
    const float* fcb    = (const float*)d_in[12];
    const float* cprojw = (const float*)d_in[13];
    const float* cprojb = (const float*)d_in[14];
    const float* lnfw   = (const float*)d_in[15];
    const float* lnfb   = (const float*)d_in[16];
    const float* headw  = (const float*)d_in[17];
    float* out = (float*)d_out;

    float *px, *ph, *pq, *pa, *pf;
    cudaGetSymbolAddress((void**)&px, g_x);
    cudaGetSymbolAddress((void**)&ph, g_h);
    cudaGetSymbolAddress((void**)&pq, g_qkv);
    cudaGetSymbolAddress((void**)&pa, g_attn);
    cudaGetSymbolAddress((void**)&pf, g_fc);

    embed_k<<<MTOK, 256>>>(idx, wte, wpe, px);

    for (int l = 0; l < LL; l++) {
        ln_k<<<MTOK, 256>>>(px, ln1w + (size_t)l * DD, ln1b + (size_t)l * DD, ph);
        gemm_nt<0><<<dim3(3 * DD / 128, MTOK / 128), 256>>>(
            ph, qkvw + (size_t)l * 3 * DD * DD, qkvb + (size_t)l * 3 * DD,
            pq, MTOK, 3 * DD, DD);
        attn_k<<<dim3(SS / 64, HH, BB), 64>>>(pq, pa);
        gemm_nt<2><<<dim3(DD / 128, MTOK / 128), 256>>>(
            pa, projw + (size_t)l * DD * DD, projb + (size_t)l * DD,
            px, MTOK, DD, DD);
        ln_k<<<MTOK, 256>>>(px, ln2w + (size_t)l * DD, ln2b + (size_t)l * DD, ph);
        gemm_nt<1><<<dim3(4 * DD / 128, MTOK / 128), 256>>>(
            ph, fcw + (size_t)l * 4 * DD * DD, fcb + (size_t)l * 4 * DD,
            pf, MTOK, 4 * DD, DD);
        gemm_nt<2><<<dim3(DD / 128, MTOK / 128), 256>>>(
            pf, cprojw + (size_t)l * DD * 4 * DD, cprojb + (size_t)l * DD,
            px, MTOK, DD, 4 * DD);
    }

    ln_k<<<MTOK, 256>>>(px, lnfw, lnfb, ph);
    gemm_nt<3><<<dim3(VV / 128, MTOK / 128), 256>>>(
        ph, headw, nullptr, out, MTOK, VV, DD);
}

// round 6
// speedup vs baseline: 1.8561x; 1.8561x over previous
#include <cuda_runtime.h>
#include <cstdint>
#include <cstddef>

// Problem constants
#define BB 4
#define SS 2048
#define DD 1024
#define HH 16
#define LL 8
#define VV 8192
#define HDIM 64
#define MTOK (BB*SS)   // 8192 tokens

typedef unsigned long long ull;

// ---------------------------------------------------------------------------
// Static device scratch (no allocations allowed)
// ---------------------------------------------------------------------------
__device__ float g_x   [(size_t)MTOK * DD];
__device__ float g_h   [(size_t)MTOK * DD];
__device__ float g_qkv [(size_t)MTOK * 3 * DD];
__device__ float g_attn[(size_t)MTOK * DD];
__device__ float g_fc  [(size_t)MTOK * 4 * DD];

// ---------------------------------------------------------------------------
// Packed f32x2 helpers
// ---------------------------------------------------------------------------
__device__ __forceinline__ void fma2(ull& d, ull a, ull b) {
    asm("fma.rn.f32x2 %0, %1, %2, %0;" : "+l"(d) : "l"(a), "l"(b));
}
__device__ __forceinline__ ull mul2(ull a, ull b) {
    ull d; asm("mul.rn.f32x2 %0, %1, %2;" : "=l"(d) : "l"(a), "l"(b)); return d;
}
__device__ __forceinline__ ull pack2(float x, float y) {
    ull d; asm("mov.b64 %0, {%1, %2};" : "=l"(d) : "f"(x), "f"(y)); return d;
}
__device__ __forceinline__ float2 unpack2(ull v) {
    float2 r; asm("mov.b64 {%0, %1}, %2;" : "=f"(r.x), "=f"(r.y) : "l"(v)); return r;
}

__device__ __forceinline__ float gelu_f(float x) {
    float z = 0.7978845608028654f * (x + 0.044715f * x * x * x);
    float e = __expf(2.0f * z);
    float th = 1.0f - 2.0f / (e + 1.0f);
    return 0.5f * x * (1.0f + th);
}

// bf16x2 pack: result = {hi(y) | lo(x)} as u32 (x in low half)
__device__ __forceinline__ uint32_t bf2(float lo, float hi) {
    uint32_t r; asm("cvt.rn.bf16x2.f32 %0, %1, %2;" : "=r"(r) : "f"(hi), "f"(lo)); return r;
}

__device__ __forceinline__ uint32_t smem_u32(const void* p) {
    uint32_t a;
    asm("{ .reg .u64 t; cvta.to.shared.u64 t, %1; cvt.u32.u64 %0, t; }" : "=r"(a) : "l"(p));
    return a;
}

// ---------------------------------------------------------------------------
// Legacy tensor core path (sm_80-compatible: works on plain sm_103 target)
// ---------------------------------------------------------------------------
__device__ __forceinline__ void ldsm4(uint32_t* r, uint32_t addr) {
    asm volatile("ldmatrix.sync.aligned.m8n8.x4.shared.b16 {%0,%1,%2,%3}, [%4];"
        : "=r"(r[0]), "=r"(r[1]), "=r"(r[2]), "=r"(r[3]) : "r"(addr));
}
__device__ __forceinline__ void ldsm2(uint32_t* r, uint32_t addr) {
    asm volatile("ldmatrix.sync.aligned.m8n8.x2.shared.b16 {%0,%1}, [%2];"
        : "=r"(r[0]), "=r"(r[1]) : "r"(addr));
}
__device__ __forceinline__ void mma16816(float* c, const uint32_t* a, const uint32_t* b) {
    asm volatile(
        "mma.sync.aligned.m16n8k16.row.col.f32.bf16.bf16.f32 "
        "{%0,%1,%2,%3}, {%4,%5,%6,%7}, {%8,%9}, {%0,%1,%2,%3};"
        : "+f"(c[0]), "+f"(c[1]), "+f"(c[2]), "+f"(c[3])
        : "r"(a[0]), "r"(a[1]), "r"(a[2]), "r"(a[3]), "r"(b[0]), "r"(b[1]));
}

// fp32 -> (bf16 hi, bf16 lo residual), 4 elems, 8B each store
__device__ __forceinline__ void cvt_store(char* hi, char* lo, float4 v) {
    uint32_t h0 = bf2(v.x, v.y);
    uint32_t h1 = bf2(v.z, v.w);
    float bx = __uint_as_float(h0 << 16);
    float by = __uint_as_float(h0 & 0xffff0000u);
    float bz = __uint_as_float(h1 << 16);
    float bw = __uint_as_float(h1 & 0xffff0000u);
    uint32_t l0 = bf2(v.x - bx, v.y - by);
    uint32_t l1 = bf2(v.z - bz, v.w - bw);
    *(ull*)hi = ((ull)h1 << 32) | h0;
    *(ull*)lo = ((ull)l1 << 32) | l0;
}

// ---------------------------------------------------------------------------
// Embedding
// ---------------------------------------------------------------------------
__global__ void embed_k(const int* __restrict__ idx, const float* __restrict__ wte,
                        const float* __restrict__ wpe, float* __restrict__ x) {
    int row = blockIdx.x;
    int s   = row & (SS - 1);
    int t   = threadIdx.x;
    int tok = idx[row];
    float4 a = ((const float4*)(wte + (size_t)tok * DD))[t];
    float4 p = ((const float4*)(wpe + (size_t)s * DD))[t];
    ((float4*)(x + (size_t)row * DD))[t] =
        make_float4(a.x + p.x, a.y + p.y, a.z + p.z, a.w + p.w);
}

// ---------------------------------------------------------------------------
// LayerNorm
// ---------------------------------------------------------------------------
__global__ void ln_k(const float* __restrict__ x, const float* __restrict__ w,
                     const float* __restrict__ b, float* __restrict__ o) {
    int row = blockIdx.x;
    int t   = threadIdx.x;
    float4 v = ((const float4*)(x + (size_t)row * DD))[t];
    float s = v.x + v.y + v.z + v.w;
    float q = v.x * v.x + v.y * v.y + v.z * v.z + v.w * v.w;
    #pragma unroll
    for (int off = 16; off; off >>= 1) {
        s += __shfl_xor_sync(0xffffffffu, s, off);
        q += __shfl_xor_sync(0xffffffffu, q, off);
    }
    __shared__ float ss[8], sq[8];
    __shared__ float smu, srs;
    int wid = t >> 5;
    if ((t & 31) == 0) { ss[wid] = s; sq[wid] = q; }
    __syncthreads();
    if (t == 0) {
        float S = 0.f, Q = 0.f;
        #pragma unroll
        for (int i = 0; i < 8; i++) { S += ss[i]; Q += sq[i]; }
        float mu  = S * (1.0f / DD);
        float var = Q * (1.0f / DD) - mu * mu;
        smu = mu;
        srs = rsqrtf(var + 1e-5f);
    }
    __syncthreads();
    float mu = smu, r = srs;
    float4 wv = ((const float4*)w)[t];
    float4 bv = ((const float4*)b)[t];
    float4 out;
    out.x = (v.x - mu) * r * wv.x + bv.x;
    out.y = (v.y - mu) * r * wv.y + bv.y;
    out.z = (v.z - mu) * r * wv.z + bv.z;
    out.w = (v.w - mu) * r * wv.w + bv.w;
    ((float4*)(o + (size_t)row * DD))[t] = out;
}

// ---------------------------------------------------------------------------
// Tensor-core NT GEMM: C[M,N] = A[M,K] @ B[N,K]^T via mma.sync bf16x3 split.
// CTA tile 128x128, K-step 32, 8 warps (2M x 4N -> 64x32 warp tiles),
// double-buffered smem, padded rows (40 bf16) for conflict-free ldmatrix.
// EPI: 0 = +bias, 1 = gelu(+bias), 2 = C += acc+bias, 3 = plain
// ---------------------------------------------------------------------------
#define ROWB 80          // bytes per padded smem row (40 bf16)
#define PL_AH 0
#define PL_AL 10240
#define PL_BH 20480
#define PL_BL 30720
#define STG   40960      // bytes per stage
#define GEMM_SMEM (2*STG)

template<int EPI>
__global__ void __launch_bounds__(256, 1)
gemm_mma(const float* __restrict__ A, const float* __restrict__ Bm,
         const float* __restrict__ bias, float* __restrict__ C,
         int M, int N, int K)
{
    extern __shared__ __align__(16) char sm[];
    int tid  = threadIdx.x;
    int lane = tid & 31;
    int w    = tid >> 5;
    int wm   = w & 1;          // 0..1  (64-row group)
    int wn   = w >> 1;         // 0..3  (32-col group)
    int bn = blockIdx.x << 7, bm = blockIdx.y << 7;

    const float* Ab = A  + (size_t)bm * K;
    const float* Bb = Bm + (size_t)bn * K;

    float acc[4][4][4];
    #pragma unroll
    for (int i = 0; i < 4; i++)
        #pragma unroll
        for (int j = 0; j < 4; j++)
            #pragma unroll
            for (int r = 0; r < 4; r++) acc[i][j][r] = 0.f;

    int nk = K >> 5;
    uint32_t smb = smem_u32(sm);

    // prefetch k-step 0 (4 float4 of A + 4 of B per thread)
    float4 pa[4], pb[4];
    #pragma unroll
    for (int i = 0; i < 4; i++) {
        int f = tid + (i << 8);
        size_t ro = (size_t)(f >> 3) * K + ((f & 7) << 2);
        pa[i] = *(const float4*)(Ab + ro);
        pb[i] = *(const float4*)(Bb + ro);
    }

    for (int t = 0; t < nk; t++) {
        int s = t & 1;
        char* st = sm + s * STG;
        #pragma unroll
        for (int i = 0; i < 4; i++) {
            int f   = tid + (i << 8);
            int off = (f >> 3) * ROWB + ((f & 7) << 3);
            cvt_store(st + PL_AH + off, st + PL_AL + off, pa[i]);
            cvt_store(st + PL_BH + off, st + PL_BL + off, pb[i]);
        }
        __syncthreads();

        if (t + 1 < nk) {
            int kc = (t + 1) << 5;
            #pragma unroll
            for (int i = 0; i < 4; i++) {
                int f = tid + (i << 8);
                size_t ro = (size_t)(f >> 3) * K + kc + ((f & 7) << 2);
                pa[i] = *(const float4*)(Ab + ro);
                pb[i] = *(const float4*)(Bb + ro);
            }
        }

        uint32_t base = smb + s * STG;
        #pragma unroll
        for (int h = 0; h < 2; h++) {
            int hc = h << 4;     // k16 half within the 32-wide step
            uint32_t ah[4][4], al[4][4], bh[4][2], bl[4][2];
            #pragma unroll
            for (int mi = 0; mi < 4; mi++) {
                int row = wm * 64 + mi * 16 + (lane & 15);
                int col = hc + ((lane >> 4) << 3);
                uint32_t ad = base + row * ROWB + col * 2;
                ldsm4(ah[mi], ad + PL_AH);
                ldsm4(al[mi], ad + PL_AL);
            }
            #pragma unroll
            for (int ni = 0; ni < 4; ni++) {
                int row = wn * 32 + ni * 8 + (lane & 7);
                int col = hc + (((lane >> 3) & 1) << 3);
                uint32_t bd = base + row * ROWB + col * 2;
                ldsm2(bh[ni], bd + PL_BH);
                ldsm2(bl[ni], bd + PL_BL);
            }
            #pragma unroll
            for (int mi = 0; mi < 4; mi++)
                #pragma unroll
                for (int ni = 0; ni < 4; ni++) {
                    mma16816(acc[mi][ni], ah[mi], bh[ni]);
                    mma16816(acc[mi][ni], ah[mi], bl[ni]);
                    mma16816(acc[mi][ni], al[mi], bh[ni]);
                }
        }
        __syncthreads();
    }

    // Epilogue: thread owns (row0,row0+8) x (col,col+1) per (mi,ni) tile
    int rbase = bm + wm * 64 + (lane >> 2);
    int cbase = bn + wn * 32 + ((lane & 3) << 1);
    #pragma unroll
    for (int mi = 0; mi < 4; mi++) {
        #pragma unroll
        for (int ni = 0; ni < 4; ni++) {
            float* cc = acc[mi][ni];
            int col  = cbase + ni * 8;
            int row0 = rbase + mi * 16;
            float b0 = 0.f, b1 = 0.f;
            if (EPI != 3) { b0 = bias[col]; b1 = bias[col + 1]; }
            #pragma unroll
            for (int half = 0; half < 2; half++) {
                int row = row0 + half * 8;
                float vx = cc[half * 2] + b0;
                float vy = cc[half * 2 + 1] + b1;
                if (EPI == 1) { vx = gelu_f(vx); vy = gelu_f(vy); }
                float* cp = C + (size_t)row * N + col;
                if (EPI == 2) {
                    float2 o = *(const float2*)cp;
                    vx += o.x; vy += o.y;
                }
                *(float2*)cp = make_float2(vx, vy);
            }
        }
    }
}

// ---------------------------------------------------------------------------
// Flash attention (causal). 128 q-rows per block, 128 threads (1 thread/row).
// K/V tiles 64x64; 4-accumulator QK dots; online softmax in f32x2.
// ---------------------------------------------------------------------------
#define ATTN_SMEM ((64*64*2 + 128*65) * 4)

__global__ __launch_bounds__(128) void attn_k(const float* __restrict__ qkv,
                                              float* __restrict__ out) {
    extern __shared__ __align__(16) float asmem[];
    float (*Ks)[64]  = (float(*)[64])asmem;
    float (*Vs)[64]  = (float(*)[64])(asmem + 64 * 64);
    float* Ssc       = asmem + 2 * 64 * 64;   // [128][65]

    int b = blockIdx.z, h = blockIdx.y, qt = blockIdx.x;
    int t = threadIdx.x;
    int row = (qt << 7) + t;

    // Q pre-scaled by exact 2^-3 (== scores/sqrt(64))
    const ulonglong2* qp =
        (const ulonglong2*)(qkv + (size_t)(b * SS + row) * (3 * DD) + DD + h * HDIM);
    ull q2[32];
    ull sc = pack2(0.125f, 0.125f);
    #pragma unroll
    for (int u = 0; u < 16; u++) {
        ulonglong2 v = qp[u];
        q2[2*u]   = mul2(v.x, sc);
        q2[2*u+1] = mul2(v.y, sc);
    }

    ull o2[32];
    #pragma unroll
    for (int u = 0; u < 32; u++) o2[u] = 0ull;
    float m = -1e30f, l = 0.0f;

    int ktmax = ((qt << 7) + 127) >> 6;   // 2*qt + 1
    for (int kt = 0; kt <= ktmax; kt++) {
        __syncthreads();
        #pragma unroll
        for (int i = 0; i < 8; i++) {
            int f = t + (i << 7);
            int r = f >> 4, c4 = f & 15;
            size_t base = (size_t)(b * SS + (kt << 6) + r) * (3 * DD) + h * HDIM;
            ((float4*)Ks[r])[c4] = ((const float4*)(qkv + base))[c4];
            ((float4*)Vs[r])[c4] = ((const float4*)(qkv + base + 2 * DD))[c4];
        }
        __syncthreads();

        int jmax = row - (kt << 6);
        if (jmax > 63) jmax = 63;

        // phase 1: scores + running tile max (4 independent accumulators)
        float tm = -1e30f;
        for (int j = 0; j < 64; j++) {
            const ulonglong2* kp = (const ulonglong2*)Ks[j];
            ull a0 = 0ull, a1 = 0ull, a2 = 0ull, a3 = 0ull;
            #pragma unroll
            for (int u = 0; u < 16; u += 2) {
                ulonglong2 k0 = kp[u], k1 = kp[u + 1];
                fma2(a0, q2[2*u],     k0.x);
                fma2(a1, q2[2*u + 1], k0.y);
                fma2(a2, q2[2*u + 2], k1.x);
                fma2(a3, q2[2*u + 3], k1.y);
            }
            float2 f0 = unpack2(a0), f1 = unpack2(a1);
            float2 f2 = unpack2(a2), f3 = unpack2(a3);
            float s = ((f0.x + f0.y) + (f1.x + f1.y)) + ((f2.x + f2.y) + (f3.x + f3.y));
            s = (j <= jmax) ? s : -1e30f;
            tm = fmaxf(tm, s);
            Ssc[t * 65 + j] = s;
        }

        // phase 2: online softmax update
        float mn = fmaxf(m, tm);
        float c  = __expf(m - mn);
        l *= c;
        ull c2 = pack2(c, c);
        #pragma unroll
        for (int u = 0; u < 32; u++) o2[u] = mul2(o2[u], c2);
        for (int j = 0; j < 64; j++) {
            float p = __expf(Ssc[t * 65 + j] - mn);
            l += p;
            ull p2 = pack2(p, p);
            const ulonglong2* vp = (const ulonglong2*)Vs[j];
            #pragma unroll
            for (int u = 0; u < 16; u++) {
                ulonglong2 vv = vp[u];
                fma2(o2[2*u],   p2, vv.x);
                fma2(o2[2*u+1], p2, vv.y);
            }
        }
        m = mn;
    }

    float inv = 1.0f / l;
    float* op = out + (size_t)(b * SS + row) * DD + h * HDIM;
    #pragma unroll
    for (int u = 0; u < 32; u++) {
        float2 f = unpack2(o2[u]);
        *(float2*)(op + 2 * u) = make_float2(f.x * inv, f.y * inv);
    }
}

// ---------------------------------------------------------------------------
// Orchestration (graph-capturable: kernel launches only)
// ---------------------------------------------------------------------------
extern "C" void kernel_launch(void* const* d_in, const int* in_sizes, int n_in,
                              void* d_out, int out_size) {
    const int*   idx    = (const int*)  d_in[0];
    const float* wte    = (const float*)d_in[1];
    const float* wpe    = (const float*)d_in[2];
    const float* ln1w   = (const float*)d_in[3];
    const float* ln1b   = (const float*)d_in[4];
    const float* qkvw   = (const float*)d_in[5];
    const float* qkvb   = (const float*)d_in[6];
    const float* projw  = (const float*)d_in[7];
    const float* projb  = (const float*)d_in[8];
    const float* ln2w   = (const float*)d_in[9];
    const float* ln2b   = (const float*)d_in[10];
    const float* fcw    = (const float*)d_in[11];
    const float* fcb    = (const float*)d_in[12];
    const float* cprojw = (const float*)d_in[13];
    const float* cprojb = (const float*)d_in[14];
    const float* lnfw   = (const float*)d_in[15];
    const float* lnfb   = (const float*)d_in[16];
    const float* headw  = (const float*)d_in[17];
    float* out = (float*)d_out;

    float *px, *ph, *pq, *pa, *pf;
    cudaGetSymbolAddress((void**)&px, g_x);
    cudaGetSymbolAddress((void**)&ph, g_h);
    cudaGetSymbolAddress((void**)&pq, g_qkv);
    cudaGetSymbolAddress((void**)&pa, g_attn);
    cudaGetSymbolAddress((void**)&pf, g_fc);

    cudaFuncSetAttribute(gemm_mma<0>, cudaFuncAttributeMaxDynamicSharedMemorySize, GEMM_SMEM);
    cudaFuncSetAttribute(gemm_mma<1>, cudaFuncAttributeMaxDynamicSharedMemorySize, GEMM_SMEM);
    cudaFuncSetAttribute(gemm_mma<2>, cudaFuncAttributeMaxDynamicSharedMemorySize, GEMM_SMEM);
    cudaFuncSetAttribute(gemm_mma<3>, cudaFuncAttributeMaxDynamicSharedMemorySize, GEMM_SMEM);
    cudaFuncSetAttribute(attn_k,      cudaFuncAttributeMaxDynamicSharedMemorySize, ATTN_SMEM);

    embed_k<<<MTOK, 256>>>(idx, wte, wpe, px);

    for (int l = 0; l < LL; l++) {
        ln_k<<<MTOK, 256>>>(px, ln1w + (size_t)l * DD, ln1b + (size_t)l * DD, ph);
        gemm_mma<0><<<dim3(3 * DD / 128, MTOK / 128), 256, GEMM_SMEM>>>(
            ph, qkvw + (size_t)l * 3 * DD * DD, qkvb + (size_t)l * 3 * DD,
            pq, MTOK, 3 * DD, DD);
        attn_k<<<dim3(SS / 128, HH, BB), 128, ATTN_SMEM>>>(pq, pa);
        gemm_mma<2><<<dim3(DD / 128, MTOK / 128), 256, GEMM_SMEM>>>(
            pa, projw + (size_t)l * DD * DD, projb + (size_t)l * DD,
            px, MTOK, DD, DD);
        ln_k<<<MTOK, 256>>>(px, ln2w + (size_t)l * DD, ln2b + (size_t)l * DD, ph);
        gemm_mma<1><<<dim3(4 * DD / 128, MTOK / 128), 256, GEMM_SMEM>>>(
            ph, fcw + (size_t)l * 4 * DD * DD, fcb + (size_t)l * 4 * DD,
            pf, MTOK, 4 * DD, DD);
        gemm_mma<2><<<dim3(DD / 128, MTOK / 128), 256, GEMM_SMEM>>>(
            pf, cprojw + (size_t)l * DD * 4 * DD, cprojb + (size_t)l * DD,
            px, MTOK, DD, 4 * DD);
    }

    ln_k<<<MTOK, 256>>>(px, lnfw, lnfb, ph);
    gemm_mma<3><<<dim3(VV / 128, MTOK / 128), 256, GEMM_SMEM>>>(
        ph, headw, nullptr, out, MTOK, VV, DD);
}